// round 14
// baseline (speedup 1.0000x reference)
#include <cuda_runtime.h>
#include <cuda_fp16.h>
#include <stdint.h>

#define NB   8
#define NC   256
#define NPIX 4096
#define KST  768      // stacked K: [x_h; x_l; x_h(reused)]
#define KSL  512      // stored slabs (hi, lo)
#define MR   320      // 32 q + 32 k + 256 v output channels
#define LOG2E 1.4426950408889634f

// ---------------- scratch (device globals; no allocation) ----------------
__device__ __half g_xs[(size_t)NB * KSL * NPIX];   // stacked x (fp16 hi/lo)
__device__ __half g_ws[MR * KST];                  // stacked weights
__device__ __half g_qT[(size_t)NB * NPIX * 32];    // [b][n][d] (q pre-scaled by log2e)
__device__ __half g_kT[(size_t)NB * NPIX * 32];    // [b][n][d]
__device__ __half g_vT[(size_t)NB * NPIX * NC];    // [b][n][c]

// ---------------- mma / ldmatrix / cp.async helpers ----------------
__device__ __forceinline__ unsigned smem_u32(const void* p) {
    return (unsigned)__cvta_generic_to_shared(p);
}
__device__ __forceinline__ uint32_t h2_as_u32(__half2 h) {
    return *reinterpret_cast<uint32_t*>(&h);
}
__device__ __forceinline__ uint32_t h2exp2(uint32_t x) {
    uint32_t r;
    asm("ex2.approx.f16x2 %0, %1;" : "=r"(r) : "r"(x));
    return r;
}
__device__ __forceinline__ float ex2f(float x) {
    float r;
    asm("ex2.approx.f32 %0, %1;" : "=f"(r) : "f"(x));
    return r;
}
__device__ __forceinline__ void ldm_x4(uint32_t* r, unsigned addr) {
    asm volatile("ldmatrix.sync.aligned.m8n8.x4.shared.b16 {%0,%1,%2,%3}, [%4];\n"
                 : "=r"(r[0]), "=r"(r[1]), "=r"(r[2]), "=r"(r[3]) : "r"(addr));
}
__device__ __forceinline__ void ldm_x4_t(uint32_t* r, unsigned addr) {
    asm volatile("ldmatrix.sync.aligned.m8n8.x4.trans.shared.b16 {%0,%1,%2,%3}, [%4];\n"
                 : "=r"(r[0]), "=r"(r[1]), "=r"(r[2]), "=r"(r[3]) : "r"(addr));
}
__device__ __forceinline__ void mma_16816(float* d, const uint32_t* a, uint32_t b0, uint32_t b1) {
    asm volatile(
        "mma.sync.aligned.m16n8k16.row.col.f32.f16.f16.f32 "
        "{%0,%1,%2,%3},{%4,%5,%6,%7},{%8,%9},{%0,%1,%2,%3};\n"
        : "+f"(d[0]), "+f"(d[1]), "+f"(d[2]), "+f"(d[3])
        : "r"(a[0]), "r"(a[1]), "r"(a[2]), "r"(a[3]), "r"(b0), "r"(b1));
}
__device__ __forceinline__ void cp_async16(unsigned dst, const void* src) {
    asm volatile("cp.async.cg.shared.global [%0], [%1], 16;\n" :: "r"(dst), "l"(src));
}
__device__ __forceinline__ void cp_commit() {
    asm volatile("cp.async.commit_group;\n");
}
template <int N>
__device__ __forceinline__ void cp_wait() {
    asm volatile("cp.async.wait_group %0;\n" :: "n"(N));
}

// ---------------- pack kernels ----------------
__global__ void pack_w_kernel(const float* __restrict__ wq, const float* __restrict__ wk,
                              const float* __restrict__ wv) {
    int idx = blockIdx.x * blockDim.x + threadIdx.x;
    if (idx >= MR * NC) return;
    int k = idx & 255;
    int m = idx >> 8;
    float w = (m < 32) ? wq[m * NC + k] * LOG2E
            : (m < 64) ? wk[(m - 32) * NC + k]
                       : wv[(m - 64) * NC + k];
    __half hi = __float2half_rn(w);
    __half lo = __float2half_rn(w - __half2float(hi));
    g_ws[m * KST + k]       = hi;
    g_ws[m * KST + 256 + k] = hi;
    g_ws[m * KST + 512 + k] = lo;
}

__global__ void pack_x_kernel(const float* __restrict__ x) {
    int idx = blockIdx.x * blockDim.x + threadIdx.x;
    const int total = NB * NC * NPIX / 4;
    if (idx >= total) return;
    float4 v = ((const float4*)x)[idx];
    int n4 = idx % (NPIX / 4);
    int t  = idx / (NPIX / 4);
    int c  = t % NC;
    int b  = t / NC;
    float f[4] = {v.x, v.y, v.z, v.w};
    __align__(8) __half hi[4], lo[4];
#pragma unroll
    for (int i = 0; i < 4; i++) {
        hi[i] = __float2half_rn(f[i]);
        lo[i] = __float2half_rn(f[i] - __half2float(hi[i]));
    }
    size_t base = ((size_t)b * KSL) * NPIX + (size_t)n4 * 4;
    *(uint2*)&g_xs[base + (size_t)c * NPIX]         = *(uint2*)&hi[0];
    *(uint2*)&g_xs[base + (size_t)(c + 256) * NPIX] = *(uint2*)&lo[0];
}

// ---------------- projection GEMM: one CTA = all 320 rows x 64 pixels ----------------
#define PA_STR 40
#define PB_STR 72
#define PTHREADS 640
// smem: a_s [320x40] halfs (25600 B) + b_s [32x72] halfs (4608 B); c_s [320x72] (46080 B) overlays
#define PSMEM 46080

__global__ __launch_bounds__(PTHREADS) void proj_kernel(const float* __restrict__ bq,
                                                        const float* __restrict__ bk,
                                                        const float* __restrict__ bv) {
    __shared__ __align__(16) char psm[PSMEM];
    __half* a_s = (__half*)psm;                 // 320 x PA_STR
    __half* b_s = (__half*)(psm + 25600);       // 32 x PB_STR
    __half* c_s = (__half*)psm;                 // 320 x PB_STR (after loop)

    int n0 = blockIdx.x * 64;
    int b  = blockIdx.y;
    int tid = threadIdx.x;
    int w = tid >> 5, lane = tid & 31;          // w = 0..19, rows [16w, 16w+16)
    int g = lane >> 2, t4 = lane & 3;

    float acc[8][4];
#pragma unroll
    for (int i = 0; i < 8; i++)
#pragma unroll
        for (int j = 0; j < 4; j++) acc[i][j] = 0.f;

    const __half* gB = &g_xs[(size_t)b * KSL * NPIX + n0];

    for (int kt = 0; kt < KST / 32; kt++) {
        int k0 = kt * 32;
        int kk = (k0 < KSL) ? k0 : (k0 - KSL);
        __syncthreads();
#pragma unroll
        for (int p = 0; p < 2; p++) {   // A: 320x32 halves = 10240, 640 thr x 2 x 8
            int e = (tid + p * PTHREADS) * 8;
            int r = e >> 5, c = e & 31;
            *(uint4*)&a_s[r * PA_STR + c] = *(const uint4*)&g_ws[r * KST + k0 + c];
        }
        if (tid < 256) {                // B: 32x64 halves = 2048
            int e = tid * 8;
            int r = e >> 6, c = e & 63;
            *(uint4*)&b_s[r * PB_STR + c] = *(const uint4*)&gB[(size_t)(kk + r) * NPIX + c];
        }
        __syncthreads();
#pragma unroll
        for (int ks = 0; ks < 2; ks++) {
            uint32_t af[4];
            {
                int row = 16 * w + (lane & 15);
                int col = 16 * ks + ((lane >= 16) ? 8 : 0);
                ldm_x4(af, smem_u32(&a_s[row * PA_STR + col]));
            }
#pragma unroll
            for (int nbp = 0; nbp < 4; nbp++) {
                uint32_t bf[4];
                int row = 16 * ks + (lane & 15);
                int col = 16 * nbp + ((lane >= 16) ? 8 : 0);
                ldm_x4_t(bf, smem_u32(&b_s[row * PB_STR + col]));
                mma_16816(acc[2 * nbp],     af, bf[0], bf[1]);
                mma_16816(acc[2 * nbp + 1], af, bf[2], bf[3]);
            }
        }
    }
    __syncthreads();
    int row_a = 16 * w + g;
    int row_b = row_a + 8;
    float bias_a = (row_a < 32) ? bq[row_a] * LOG2E : (row_a < 64) ? bk[row_a - 32] : bv[row_a - 64];
    float bias_b = (row_b < 32) ? bq[row_b] * LOG2E : (row_b < 64) ? bk[row_b - 32] : bv[row_b - 64];
#pragma unroll
    for (int nt = 0; nt < 8; nt++) {
        int col = 8 * nt + 2 * t4;
        c_s[row_a * PB_STR + col]     = __float2half_rn(acc[nt][0] + bias_a);
        c_s[row_a * PB_STR + col + 1] = __float2half_rn(acc[nt][1] + bias_a);
        c_s[row_b * PB_STR + col]     = __float2half_rn(acc[nt][2] + bias_b);
        c_s[row_b * PB_STR + col + 1] = __float2half_rn(acc[nt][3] + bias_b);
    }
    __syncthreads();
    // transposed coalesced writeback: 10 parts x 32 rows x 64 pixels
    int n = tid & 63, part = tid >> 6;  // part 0..9
    __align__(16) __half tmp[32];
#pragma unroll
    for (int j = 0; j < 32; j++) tmp[j] = c_s[(part * 32 + j) * PB_STR + n];
    int ng = n0 + n;
    __half* dst;
    if (part == 0)      dst = &g_qT[((size_t)b * NPIX + ng) * 32];
    else if (part == 1) dst = &g_kT[((size_t)b * NPIX + ng) * 32];
    else                dst = &g_vT[((size_t)b * NPIX + ng) * NC + (part - 2) * 32];
#pragma unroll
    for (int q = 0; q < 4; q++) ((uint4*)dst)[q] = ((uint4*)tmp)[q];
}

// ---------------- flash attention: 128 q x 256 ch per CTA, 512 thr, 128-key chunks ----------------
#define CK   128                       // keys per load chunk (processed as 4x32)
#define VSTR 264                       // smem halves per V row (256 + 8 pad)
#define KTILE_B (CK * 40 * 2)          // 10240
#define VTILE_B (CK * VSTR * 2)        // 67584
#define OFF_Q 0                        // 128 x 40 halfs = 10240 B
#define OFF_K 10240                    // 2 stages
#define OFF_V (OFF_K + 2 * KTILE_B)    // 30720, 2 stages
#define SMEM_TOTAL (OFF_V + 2 * VTILE_B)  // 165888

__device__ __forceinline__ void flash_load_chunk(uint32_t smem_base, int buf, int b, int j0,
                                                 int tid) {
    {   // K chunk 128x32 (all 512 threads)
        int e = tid * 8;
        int r = e >> 5, c = e & 31;
        cp_async16(smem_base + OFF_K + buf * KTILE_B + (r * 40 + c) * 2,
                   &g_kT[((size_t)b * NPIX + j0 + r) * 32 + c]);
    }
#pragma unroll
    for (int p = 0; p < 8; p++) {  // V chunk 128x256
        int e = (tid + p * 512) * 8;
        int r = e >> 8, c = e & 255;
        cp_async16(smem_base + OFF_V + buf * VTILE_B + (r * VSTR + c) * 2,
                   &g_vT[((size_t)b * NPIX + j0 + r) * NC + c]);
    }
}

__global__ __launch_bounds__(512, 1) void flash_kernel(float* __restrict__ out) {
    extern __shared__ char smem_raw[];
    uint32_t smem_base = smem_u32(smem_raw);
    __half* q_s = (__half*)(smem_raw + OFF_Q);

    int nq0 = blockIdx.x * 128;
    int b   = blockIdx.y;
    int tid = threadIdx.x;
    int w = tid >> 5, lane = tid & 31, g = lane >> 2, t4 = lane & 3;
    int mw = w & 7;       // query row group: rows [16*mw, 16*mw+16)
    int nh = w >> 3;      // channel half for PV: chans [128*nh, +128)

    {   // load Q tile (128x32)
        int e = tid * 8;
        int r = e >> 5, c = e & 31;
        *(uint4*)&q_s[r * 40 + c] = *(const uint4*)&g_qT[((size_t)b * NPIX + nq0 + r) * 32 + c];
    }

    // prefetch chunk 0
    flash_load_chunk(smem_base, 0, b, 0, tid);
    cp_commit();

    float acc[16][4];
#pragma unroll
    for (int i = 0; i < 16; i++)
#pragma unroll
        for (int j = 0; j < 4; j++) acc[i][j] = 0.f;
    float l0 = 0.f, l1 = 0.f;          // per-lane PARTIAL row sums (quad-reduced at end)
    float m0 = -1e30f, m1 = -1e30f;

    __syncthreads();  // Q visible
    uint32_t qa[2][4];
#pragma unroll
    for (int ks = 0; ks < 2; ks++) {
        int row = 16 * mw + (lane & 15);
        int col = 16 * ks + ((lane >= 16) ? 8 : 0);
        ldm_x4(qa[ks], smem_u32(&q_s[row * 40 + col]));
    }

    const int NCHUNK = NPIX / CK;  // 32
#pragma unroll 1
    for (int kc = 0; kc < NCHUNK; kc++) {
        int buf = kc & 1;
        cp_wait<0>();
        __syncthreads();  // chunk kc visible; all warps done reading buf^1
        if (kc + 1 < NCHUNK) {
            flash_load_chunk(smem_base, buf ^ 1, b, (kc + 1) * CK, tid);
            cp_commit();
        }

        __half* k_s = (__half*)(smem_raw + OFF_K + buf * KTILE_B);
        __half* v_s = (__half*)(smem_raw + OFF_V + buf * VTILE_B);

#pragma unroll
        for (int s = 0; s < 4; s++) {   // 32-key sub-chunks
            // ---- S' = Q' K^T (log2 domain): 16 rows x 32 keys ----
            float sacc[4][4];
#pragma unroll
            for (int i = 0; i < 4; i++)
#pragma unroll
                for (int j = 0; j < 4; j++) sacc[i][j] = 0.f;
#pragma unroll
            for (int ks = 0; ks < 2; ks++) {
#pragma unroll
                for (int nbp = 0; nbp < 2; nbp++) {
                    uint32_t bf[4];
                    int key = 32 * s + nbp * 16 + (lane & 7) + ((lane >= 16) ? 8 : 0);
                    int col = 16 * ks + ((lane & 8) ? 8 : 0);
                    ldm_x4(bf, smem_u32(&k_s[key * 40 + col]));
                    mma_16816(sacc[2 * nbp],     qa[ks], bf[0], bf[1]);
                    mma_16816(sacc[2 * nbp + 1], qa[ks], bf[2], bf[3]);
                }
            }

            // ---- online softmax (base-2), rescale only when a max improves ----
            float mx0 = sacc[0][0], mx1 = sacc[0][2];
#pragma unroll
            for (int j = 0; j < 4; j++) {
                mx0 = fmaxf(mx0, fmaxf(sacc[j][0], sacc[j][1]));
                mx1 = fmaxf(mx1, fmaxf(sacc[j][2], sacc[j][3]));
            }
#pragma unroll
            for (int off = 1; off < 4; off <<= 1) {
                mx0 = fmaxf(mx0, __shfl_xor_sync(0xffffffffu, mx0, off));
                mx1 = fmaxf(mx1, __shfl_xor_sync(0xffffffffu, mx1, off));
            }
            bool need = __any_sync(0xffffffffu, (mx0 > m0) || (mx1 > m1));
            if (need) {
                float mn0 = fmaxf(m0, mx0), mn1 = fmaxf(m1, mx1);
                float al0 = ex2f(m0 - mn0), al1 = ex2f(m1 - mn1);
                m0 = mn0; m1 = mn1;
#pragma unroll
                for (int nt = 0; nt < 16; nt++) {
                    acc[nt][0] *= al0; acc[nt][1] *= al0;
                    acc[nt][2] *= al1; acc[nt][3] *= al1;
                }
                l0 *= al0; l1 *= al1;
            }

            // P fragments via f16x2 ex2; accumulate l partials on the fma pipe
            uint32_t pa[2][4];
#pragma unroll
            for (int t = 0; t < 2; t++) {
                pa[t][0] = h2exp2(h2_as_u32(__floats2half2_rn(sacc[2 * t][0] - m0,     sacc[2 * t][1] - m0)));
                pa[t][1] = h2exp2(h2_as_u32(__floats2half2_rn(sacc[2 * t][2] - m1,     sacc[2 * t][3] - m1)));
                pa[t][2] = h2exp2(h2_as_u32(__floats2half2_rn(sacc[2 * t + 1][0] - m0, sacc[2 * t + 1][1] - m0)));
                pa[t][3] = h2exp2(h2_as_u32(__floats2half2_rn(sacc[2 * t + 1][2] - m1, sacc[2 * t + 1][3] - m1)));
                float2 f0 = __half22float2(*reinterpret_cast<__half2*>(&pa[t][0]));
                float2 f1 = __half22float2(*reinterpret_cast<__half2*>(&pa[t][1]));
                float2 f2 = __half22float2(*reinterpret_cast<__half2*>(&pa[t][2]));
                float2 f3 = __half22float2(*reinterpret_cast<__half2*>(&pa[t][3]));
                l0 += (f0.x + f0.y) + (f2.x + f2.y);
                l1 += (f1.x + f1.y) + (f3.x + f3.y);
            }

            // ---- O += P V : 16 rows x 128 channels ----
#pragma unroll
            for (int t = 0; t < 2; t++) {
#pragma unroll
                for (int nbp = 0; nbp < 8; nbp++) {
                    uint32_t bf[4];
                    int key  = 32 * s + 16 * t + (lane & 15);
                    int chan = nh * 128 + 16 * nbp + ((lane >= 16) ? 8 : 0);
                    ldm_x4_t(bf, smem_u32(&v_s[key * VSTR + chan]));
                    mma_16816(acc[2 * nbp],     pa[t], bf[0], bf[1]);
                    mma_16816(acc[2 * nbp + 1], pa[t], bf[2], bf[3]);
                }
            }
        }
    }

    // quad-reduce l partials (lanes within a quad hold disjoint key subsets)
#pragma unroll
    for (int off = 1; off < 4; off <<= 1) {
        l0 += __shfl_xor_sync(0xffffffffu, l0, off);
        l1 += __shfl_xor_sync(0xffffffffu, l1, off);
    }

    // ---- finalize: divide by l, direct fragment writeback ----
    float inv0 = 1.f / l0;
    float inv1 = 1.f / l1;
    int r0 = nq0 + 16 * mw + g;
    int r1 = r0 + 8;
#pragma unroll
    for (int nt = 0; nt < 16; nt++) {
        int c = nh * 128 + 8 * nt + 2 * t4;
        size_t base0 = ((size_t)b * NC + c) * NPIX;
        size_t base1 = ((size_t)b * NC + c + 1) * NPIX;
        out[base0 + r0] = acc[nt][0] * inv0;
        out[base1 + r0] = acc[nt][1] * inv0;
        out[base0 + r1] = acc[nt][2] * inv1;
        out[base1 + r1] = acc[nt][3] * inv1;
    }
}

// ---------------- launcher ----------------
extern "C" void kernel_launch(void* const* d_in, const int* in_sizes, int n_in,
                              void* d_out, int out_size) {
    (void)in_sizes; (void)n_in; (void)out_size;
    const float* x  = (const float*)d_in[0];
    const float* wq = (const float*)d_in[1];
    const float* bq = (const float*)d_in[2];
    const float* wk = (const float*)d_in[3];
    const float* bk = (const float*)d_in[4];
    const float* wv = (const float*)d_in[5];
    const float* bv = (const float*)d_in[6];
    float* out = (float*)d_out;

    pack_w_kernel<<<(MR * NC + 255) / 256, 256>>>(wq, wk, wv);
    pack_x_kernel<<<(NB * NC * NPIX / 4 + 255) / 256, 256>>>(x);

    dim3 pg(NPIX / 64, NB);
    proj_kernel<<<pg, PTHREADS>>>(bq, bk, bv);

    cudaFuncSetAttribute(flash_kernel, cudaFuncAttributeMaxDynamicSharedMemorySize, SMEM_TOTAL);
    dim3 fg(NPIX / 128, NB);
    flash_kernel<<<fg, 512, SMEM_TOTAL>>>(out);
}

// round 17
// speedup vs baseline: 1.7509x; 1.7509x over previous
#include <cuda_runtime.h>
#include <cuda_fp16.h>
#include <stdint.h>

#define NB   8
#define NC   256
#define NPIX 4096
#define KST  768      // stacked K: [x_h; x_l; x_h(reused)]
#define KSL  512      // stored slabs (hi, lo)
#define MR   320      // 32 q + 32 k + 256 v output channels
#define LOG2E 1.4426950408889634f

// ---------------- scratch (device globals; no allocation) ----------------
__device__ __half g_xs[(size_t)NB * KSL * NPIX];   // stacked x (fp16 hi/lo)
__device__ __half g_ws[MR * KST];                  // stacked weights
__device__ __half g_qT[(size_t)NB * NPIX * 32];    // [b][n][d] (q pre-scaled by log2e)
__device__ __half g_kT[(size_t)NB * NPIX * 32];    // [b][n][d]
__device__ __half g_vT[(size_t)NB * NPIX * NC];    // [b][n][c]

// ---------------- mma / ldmatrix / cp.async helpers ----------------
__device__ __forceinline__ unsigned smem_u32(const void* p) {
    return (unsigned)__cvta_generic_to_shared(p);
}
__device__ __forceinline__ uint32_t h2_as_u32(__half2 h) {
    return *reinterpret_cast<uint32_t*>(&h);
}
__device__ __forceinline__ uint32_t h2exp2(uint32_t x) {
    uint32_t r;
    asm("ex2.approx.f16x2 %0, %1;" : "=r"(r) : "r"(x));
    return r;
}
__device__ __forceinline__ float ex2f(float x) {
    float r;
    asm("ex2.approx.f32 %0, %1;" : "=f"(r) : "f"(x));
    return r;
}
__device__ __forceinline__ void ldm_x4(uint32_t* r, unsigned addr) {
    asm volatile("ldmatrix.sync.aligned.m8n8.x4.shared.b16 {%0,%1,%2,%3}, [%4];\n"
                 : "=r"(r[0]), "=r"(r[1]), "=r"(r[2]), "=r"(r[3]) : "r"(addr));
}
__device__ __forceinline__ void ldm_x4_t(uint32_t* r, unsigned addr) {
    asm volatile("ldmatrix.sync.aligned.m8n8.x4.trans.shared.b16 {%0,%1,%2,%3}, [%4];\n"
                 : "=r"(r[0]), "=r"(r[1]), "=r"(r[2]), "=r"(r[3]) : "r"(addr));
}
__device__ __forceinline__ void mma_16816(float* d, const uint32_t* a, uint32_t b0, uint32_t b1) {
    asm volatile(
        "mma.sync.aligned.m16n8k16.row.col.f32.f16.f16.f32 "
        "{%0,%1,%2,%3},{%4,%5,%6,%7},{%8,%9},{%0,%1,%2,%3};\n"
        : "+f"(d[0]), "+f"(d[1]), "+f"(d[2]), "+f"(d[3])
        : "r"(a[0]), "r"(a[1]), "r"(a[2]), "r"(a[3]), "r"(b0), "r"(b1));
}
__device__ __forceinline__ void cp_async16(unsigned dst, const void* src) {
    asm volatile("cp.async.cg.shared.global [%0], [%1], 16;\n" :: "r"(dst), "l"(src));
}
__device__ __forceinline__ void cp_commit() {
    asm volatile("cp.async.commit_group;\n");
}
template <int N>
__device__ __forceinline__ void cp_wait() {
    asm volatile("cp.async.wait_group %0;\n" :: "n"(N));
}

// ---------------- pack kernels ----------------
__global__ void pack_w_kernel(const float* __restrict__ wq, const float* __restrict__ wk,
                              const float* __restrict__ wv) {
    int idx = blockIdx.x * blockDim.x + threadIdx.x;
    if (idx >= MR * NC) return;
    int k = idx & 255;
    int m = idx >> 8;
    float w = (m < 32) ? wq[m * NC + k] * LOG2E
            : (m < 64) ? wk[(m - 32) * NC + k]
                       : wv[(m - 64) * NC + k];
    __half hi = __float2half_rn(w);
    __half lo = __float2half_rn(w - __half2float(hi));
    g_ws[m * KST + k]       = hi;
    g_ws[m * KST + 256 + k] = hi;
    g_ws[m * KST + 512 + k] = lo;
}

__global__ void pack_x_kernel(const float* __restrict__ x) {
    int idx = blockIdx.x * blockDim.x + threadIdx.x;
    const int total = NB * NC * NPIX / 4;
    if (idx >= total) return;
    float4 v = ((const float4*)x)[idx];
    int n4 = idx % (NPIX / 4);
    int t  = idx / (NPIX / 4);
    int c  = t % NC;
    int b  = t / NC;
    float f[4] = {v.x, v.y, v.z, v.w};
    __align__(8) __half hi[4], lo[4];
#pragma unroll
    for (int i = 0; i < 4; i++) {
        hi[i] = __float2half_rn(f[i]);
        lo[i] = __float2half_rn(f[i] - __half2float(hi[i]));
    }
    size_t base = ((size_t)b * KSL) * NPIX + (size_t)n4 * 4;
    *(uint2*)&g_xs[base + (size_t)c * NPIX]         = *(uint2*)&hi[0];
    *(uint2*)&g_xs[base + (size_t)(c + 256) * NPIX] = *(uint2*)&lo[0];
}

// ---------------- projection GEMM: C[320,4096] = Ws[320,768] * Xs[768,4096] ----------------
// 64-deep k-tiles: per iteration stage A 64x64 + B 64x64, run 4 MMA k-steps.
#define PAB_STR 72

__global__ __launch_bounds__(128) void proj_kernel(const float* __restrict__ bq,
                                                   const float* __restrict__ bk,
                                                   const float* __restrict__ bv) {
    __shared__ __half a_s[64 * PAB_STR];
    __shared__ __half b_s[64 * PAB_STR];
    __shared__ __half c_s[64 * PAB_STR];

    int n0 = blockIdx.x * 64;
    int m0 = blockIdx.y * 64;
    int b  = blockIdx.z;
    int tid = threadIdx.x;
    int w = tid >> 5, lane = tid & 31;
    int g = lane >> 2, t4 = lane & 3;

    float acc[8][4];
#pragma unroll
    for (int i = 0; i < 8; i++)
#pragma unroll
        for (int j = 0; j < 4; j++) acc[i][j] = 0.f;

    const __half* gA = &g_ws[m0 * KST];
    const __half* gB = &g_xs[(size_t)b * KSL * NPIX + n0];

    for (int kt = 0; kt < KST / 64; kt++) {      // 12 iterations
        int k0 = kt * 64;
        int kk = (k0 < KSL) ? k0 : (k0 - KSL);   // hi slab re-read for lo-weight rows
        __syncthreads();
#pragma unroll
        for (int p = 0; p < 4; p++) {            // A: 64 rows x 64 k-cols
            int e = (tid + p * 128) * 8;
            int r = e >> 6, c = e & 63;
            *(uint4*)&a_s[r * PAB_STR + c] = *(const uint4*)&gA[r * KST + k0 + c];
        }
#pragma unroll
        for (int p = 0; p < 4; p++) {            // B: 64 k-rows x 64 pixels
            int e = (tid + p * 128) * 8;
            int r = e >> 6, c = e & 63;
            *(uint4*)&b_s[r * PAB_STR + c] = *(const uint4*)&gB[(size_t)(kk + r) * NPIX + c];
        }
        __syncthreads();
#pragma unroll
        for (int ks = 0; ks < 4; ks++) {
            uint32_t af[4];
            {
                int row = 16 * w + (lane & 15);
                int col = 16 * ks + ((lane >= 16) ? 8 : 0);
                ldm_x4(af, smem_u32(&a_s[row * PAB_STR + col]));
            }
#pragma unroll
            for (int nbp = 0; nbp < 4; nbp++) {
                uint32_t bf[4];
                int row = 16 * ks + (lane & 15);
                int col = 16 * nbp + ((lane >= 16) ? 8 : 0);
                ldm_x4_t(bf, smem_u32(&b_s[row * PAB_STR + col]));
                mma_16816(acc[2 * nbp],     af, bf[0], bf[1]);
                mma_16816(acc[2 * nbp + 1], af, bf[2], bf[3]);
            }
        }
    }
    __syncthreads();
    int row_a = 16 * w + g;
    int row_b = row_a + 8;
    int ma = m0 + row_a, mb = m0 + row_b;
    float bias_a = (ma < 32) ? bq[ma] * LOG2E : (ma < 64) ? bk[ma - 32] : bv[ma - 64];
    float bias_b = (mb < 32) ? bq[mb] * LOG2E : (mb < 64) ? bk[mb - 32] : bv[mb - 64];
#pragma unroll
    for (int nt = 0; nt < 8; nt++) {
        int col = 8 * nt + 2 * t4;
        c_s[row_a * PAB_STR + col]     = __float2half_rn(acc[nt][0] + bias_a);
        c_s[row_a * PAB_STR + col + 1] = __float2half_rn(acc[nt][1] + bias_a);
        c_s[row_b * PAB_STR + col]     = __float2half_rn(acc[nt][2] + bias_b);
        c_s[row_b * PAB_STR + col + 1] = __float2half_rn(acc[nt][3] + bias_b);
    }
    __syncthreads();
    // transposed coalesced writeback
    int n = tid & 63, part = tid >> 6;
    __align__(16) __half tmp[32];
#pragma unroll
    for (int j = 0; j < 32; j++) tmp[j] = c_s[(part * 32 + j) * PAB_STR + n];
    int ng = n0 + n;
    __half* dst;
    if (m0 == 0) {
        dst = (part == 0) ? &g_qT[((size_t)b * NPIX + ng) * 32]
                          : &g_kT[((size_t)b * NPIX + ng) * 32];
    } else {
        int cb = (m0 - 64) + part * 32;
        dst = &g_vT[((size_t)b * NPIX + ng) * NC + cb];
    }
#pragma unroll
    for (int q = 0; q < 4; q++) ((uint4*)dst)[q] = ((uint4*)tmp)[q];
}

// ---------------- flash attention: 128 q x 256 ch per CTA, 512 thr, 128-key chunks ----------------
#define CK   128                       // keys per load chunk (processed as 4x32)
#define VSTR 264                       // smem halves per V row (256 + 8 pad)
#define KTILE_B (CK * 40 * 2)          // 10240
#define VTILE_B (CK * VSTR * 2)        // 67584
#define OFF_Q 0                        // 128 x 40 halfs = 10240 B
#define OFF_K 10240                    // 2 stages
#define OFF_V (OFF_K + 2 * KTILE_B)    // 30720, 2 stages
#define SMEM_TOTAL (OFF_V + 2 * VTILE_B)  // 165888
#define ONES_H2 0x3C003C00u

__device__ __forceinline__ void flash_load_chunk(uint32_t smem_base, int buf, int b, int j0,
                                                 int tid) {
    {   // K chunk 128x32 (all 512 threads)
        int e = tid * 8;
        int r = e >> 5, c = e & 31;
        cp_async16(smem_base + OFF_K + buf * KTILE_B + (r * 40 + c) * 2,
                   &g_kT[((size_t)b * NPIX + j0 + r) * 32 + c]);
    }
#pragma unroll
    for (int p = 0; p < 8; p++) {  // V chunk 128x256
        int e = (tid + p * 512) * 8;
        int r = e >> 8, c = e & 255;
        cp_async16(smem_base + OFF_V + buf * VTILE_B + (r * VSTR + c) * 2,
                   &g_vT[((size_t)b * NPIX + j0 + r) * NC + c]);
    }
}

__global__ __launch_bounds__(512, 1) void flash_kernel(float* __restrict__ out) {
    extern __shared__ char smem_raw[];
    uint32_t smem_base = smem_u32(smem_raw);
    __half* q_s = (__half*)(smem_raw + OFF_Q);

    int nq0 = blockIdx.x * 128;
    int b   = blockIdx.y;
    int tid = threadIdx.x;
    int w = tid >> 5, lane = tid & 31, g = lane >> 2, t4 = lane & 3;
    int mw = w & 7;       // query row group: rows [16*mw, 16*mw+16)
    int nh = w >> 3;      // channel half for PV: chans [128*nh, +128)

    {   // load Q tile (128x32)
        int e = tid * 8;
        int r = e >> 5, c = e & 31;
        *(uint4*)&q_s[r * 40 + c] = *(const uint4*)&g_qT[((size_t)b * NPIX + nq0 + r) * 32 + c];
    }

    // prefetch chunk 0
    flash_load_chunk(smem_base, 0, b, 0, tid);
    cp_commit();

    float acc[16][4];
#pragma unroll
    for (int i = 0; i < 16; i++)
#pragma unroll
        for (int j = 0; j < 4; j++) acc[i][j] = 0.f;
    float lacc[4] = {0.f, 0.f, 0.f, 0.f};
    float m0 = -1e30f, m1 = -1e30f;

    __syncthreads();  // Q visible
    uint32_t qa[2][4];
#pragma unroll
    for (int ks = 0; ks < 2; ks++) {
        int row = 16 * mw + (lane & 15);
        int col = 16 * ks + ((lane >= 16) ? 8 : 0);
        ldm_x4(qa[ks], smem_u32(&q_s[row * 40 + col]));
    }

    const int NCHUNK = NPIX / CK;  // 32
#pragma unroll 1
    for (int kc = 0; kc < NCHUNK; kc++) {
        int buf = kc & 1;
        cp_wait<0>();
        __syncthreads();  // chunk kc visible; all warps done reading buf^1
        if (kc + 1 < NCHUNK) {
            flash_load_chunk(smem_base, buf ^ 1, b, (kc + 1) * CK, tid);
            cp_commit();
        }

        __half* k_s = (__half*)(smem_raw + OFF_K + buf * KTILE_B);
        __half* v_s = (__half*)(smem_raw + OFF_V + buf * VTILE_B);

#pragma unroll
        for (int s = 0; s < 4; s++) {   // 32-key sub-chunks
            // ---- S' = Q' K^T (log2 domain): 16 rows x 32 keys ----
            float sacc[4][4];
#pragma unroll
            for (int i = 0; i < 4; i++)
#pragma unroll
                for (int j = 0; j < 4; j++) sacc[i][j] = 0.f;
#pragma unroll
            for (int ks = 0; ks < 2; ks++) {
#pragma unroll
                for (int nbp = 0; nbp < 2; nbp++) {
                    uint32_t bf[4];
                    int key = 32 * s + nbp * 16 + (lane & 7) + ((lane >= 16) ? 8 : 0);
                    int col = 16 * ks + ((lane & 8) ? 8 : 0);
                    ldm_x4(bf, smem_u32(&k_s[key * 40 + col]));
                    mma_16816(sacc[2 * nbp],     qa[ks], bf[0], bf[1]);
                    mma_16816(sacc[2 * nbp + 1], qa[ks], bf[2], bf[3]);
                }
            }

            // ---- online softmax (base-2), rescale only when a max improves ----
            float mx0 = sacc[0][0], mx1 = sacc[0][2];
#pragma unroll
            for (int j = 0; j < 4; j++) {
                mx0 = fmaxf(mx0, fmaxf(sacc[j][0], sacc[j][1]));
                mx1 = fmaxf(mx1, fmaxf(sacc[j][2], sacc[j][3]));
            }
#pragma unroll
            for (int off = 1; off < 4; off <<= 1) {
                mx0 = fmaxf(mx0, __shfl_xor_sync(0xffffffffu, mx0, off));
                mx1 = fmaxf(mx1, __shfl_xor_sync(0xffffffffu, mx1, off));
            }
            bool need = __any_sync(0xffffffffu, (mx0 > m0) || (mx1 > m1));
            if (need) {
                float mn0 = fmaxf(m0, mx0), mn1 = fmaxf(m1, mx1);
                float al0 = ex2f(m0 - mn0), al1 = ex2f(m1 - mn1);
                m0 = mn0; m1 = mn1;
#pragma unroll
                for (int nt = 0; nt < 16; nt++) {
                    acc[nt][0] *= al0; acc[nt][1] *= al0;
                    acc[nt][2] *= al1; acc[nt][3] *= al1;
                }
                lacc[0] *= al0; lacc[1] *= al0; lacc[2] *= al1; lacc[3] *= al1;
            }

            // P fragments via f16x2 ex2
            uint32_t pa[2][4];
#pragma unroll
            for (int t = 0; t < 2; t++) {
                pa[t][0] = h2exp2(h2_as_u32(__floats2half2_rn(sacc[2 * t][0] - m0,     sacc[2 * t][1] - m0)));
                pa[t][1] = h2exp2(h2_as_u32(__floats2half2_rn(sacc[2 * t][2] - m1,     sacc[2 * t][3] - m1)));
                pa[t][2] = h2exp2(h2_as_u32(__floats2half2_rn(sacc[2 * t + 1][0] - m0, sacc[2 * t + 1][1] - m0)));
                pa[t][3] = h2exp2(h2_as_u32(__floats2half2_rn(sacc[2 * t + 1][2] - m1, sacc[2 * t + 1][3] - m1)));
            }

            // ---- O += P V : 16 rows x 128 channels ----
#pragma unroll
            for (int t = 0; t < 2; t++) {
#pragma unroll
                for (int nbp = 0; nbp < 8; nbp++) {
                    uint32_t bf[4];
                    int key  = 32 * s + 16 * t + (lane & 15);
                    int chan = nh * 128 + 16 * nbp + ((lane >= 16) ? 8 : 0);
                    ldm_x4_t(bf, smem_u32(&v_s[key * VSTR + chan]));
                    mma_16816(acc[2 * nbp],     pa[t], bf[0], bf[1]);
                    mma_16816(acc[2 * nbp + 1], pa[t], bf[2], bf[3]);
                }
                mma_16816(lacc, pa[t], ONES_H2, ONES_H2);
            }
        }
    }

    // ---- finalize: divide by l, direct fragment writeback ----
    float inv0 = 1.f / lacc[0];
    float inv1 = 1.f / lacc[2];
    int r0 = nq0 + 16 * mw + g;
    int r1 = r0 + 8;
#pragma unroll
    for (int nt = 0; nt < 16; nt++) {
        int c = nh * 128 + 8 * nt + 2 * t4;
        size_t base0 = ((size_t)b * NC + c) * NPIX;
        size_t base1 = ((size_t)b * NC + c + 1) * NPIX;
        out[base0 + r0] = acc[nt][0] * inv0;
        out[base1 + r0] = acc[nt][1] * inv0;
        out[base0 + r1] = acc[nt][2] * inv1;
        out[base1 + r1] = acc[nt][3] * inv1;
    }
}

// ---------------- launcher ----------------
extern "C" void kernel_launch(void* const* d_in, const int* in_sizes, int n_in,
                              void* d_out, int out_size) {
    (void)in_sizes; (void)n_in; (void)out_size;
    const float* x  = (const float*)d_in[0];
    const float* wq = (const float*)d_in[1];
    const float* bq = (const float*)d_in[2];
    const float* wk = (const float*)d_in[3];
    const float* bk = (const float*)d_in[4];
    const float* wv = (const float*)d_in[5];
    const float* bv = (const float*)d_in[6];
    float* out = (float*)d_out;

    pack_w_kernel<<<(MR * NC + 255) / 256, 256>>>(wq, wk, wv);
    pack_x_kernel<<<(NB * NC * NPIX / 4 + 255) / 256, 256>>>(x);

    dim3 pg(NPIX / 64, MR / 64, NB);
    proj_kernel<<<pg, 128>>>(bq, bk, bv);

    cudaFuncSetAttribute(flash_kernel, cudaFuncAttributeMaxDynamicSharedMemorySize, SMEM_TOTAL);
    dim3 fg(NPIX / 128, NB);
    flash_kernel<<<fg, 512, SMEM_TOTAL>>>(out);
}